// round 1
// baseline (speedup 1.0000x reference)
#include <cuda_runtime.h>

#define HH 16
#define NN 8192
#define DD 64
#define WW 128
#define TS 32
#define NEGINF (-1e30f)

// Pooled K/V scratch (allocation-free: __device__ globals)
__device__ float g_k1[HH * 1024 * DD];
__device__ float g_v1[HH * 1024 * DD];
__device__ float g_k2[HH * 128 * DD];
__device__ float g_v2[HH * 128 * DD];
__device__ float g_k3[HH * 16 * DD];
__device__ float g_v3[HH * 16 * DD];

// ---------------- pooling kernels ----------------
__global__ void pool1_kernel(const float* __restrict__ k, const float* __restrict__ v) {
    int idx = blockIdx.x * blockDim.x + threadIdx.x;
    if (idx >= HH * 1024 * DD) return;
    int dd = idx & (DD - 1);
    int c  = (idx / DD) & 1023;
    int h  = idx / (DD * 1024);
    const float* ks = k + ((size_t)h * NN + (size_t)c * 8) * DD + dd;
    const float* vs = v + ((size_t)h * NN + (size_t)c * 8) * DD + dd;
    float sk = 0.f, sv = 0.f;
#pragma unroll
    for (int r = 0; r < 8; r++) { sk += ks[r * DD]; sv += vs[r * DD]; }
    g_k1[idx] = sk * 0.125f;
    g_v1[idx] = sv * 0.125f;
}

__global__ void pool2_kernel() {
    int idx = blockIdx.x * blockDim.x + threadIdx.x;
    if (idx >= HH * 128 * DD) return;
    int dd = idx & (DD - 1);
    int c  = (idx / DD) & 127;
    int h  = idx / (DD * 128);
    const float* ks = g_k1 + ((size_t)h * 1024 + (size_t)c * 8) * DD + dd;
    const float* vs = g_v1 + ((size_t)h * 1024 + (size_t)c * 8) * DD + dd;
    float sk = 0.f, sv = 0.f;
#pragma unroll
    for (int r = 0; r < 8; r++) { sk += ks[r * DD]; sv += vs[r * DD]; }
    g_k2[idx] = sk * 0.125f;
    g_v2[idx] = sv * 0.125f;
}

__global__ void pool3_kernel() {
    int idx = blockIdx.x * blockDim.x + threadIdx.x;
    if (idx >= HH * 16 * DD) return;
    int dd = idx & (DD - 1);
    int c  = (idx / DD) & 15;
    int h  = idx / (DD * 16);
    const float* ks = g_k2 + ((size_t)h * 128 + (size_t)c * 8) * DD + dd;
    const float* vs = g_v2 + ((size_t)h * 128 + (size_t)c * 8) * DD + dd;
    float sk = 0.f, sv = 0.f;
#pragma unroll
    for (int r = 0; r < 8; r++) { sk += ks[r * DD]; sv += vs[r * DD]; }
    g_k3[idx] = sk * 0.125f;
    g_v3[idx] = sv * 0.125f;
}

// ---------------- attention ----------------
// Online-softmax update for one visible key/chunk.
// Branchy: when running max m is not exceeded (common case with nearest-first
// ordering + ALiBi decay), the o-update is a single FMA per dim.
__device__ __forceinline__ void dot_update(
    const float4* __restrict__ krow, const float4* __restrict__ vrow,
    const float4* __restrict__ qr, float sc_bias,
    float& m, float& l, float* __restrict__ o)
{
    float a0 = 0.f, a1 = 0.f, a2 = 0.f, a3 = 0.f;
#pragma unroll
    for (int t = 0; t < 16; t++) {
        float4 kk = krow[t];
        a0 = fmaf(qr[t].x, kk.x, a0);
        a1 = fmaf(qr[t].y, kk.y, a1);
        a2 = fmaf(qr[t].z, kk.z, a2);
        a3 = fmaf(qr[t].w, kk.w, a3);
    }
    float sc = (a0 + a1 + a2 + a3) * 0.125f + sc_bias;
    if (sc <= m) {
        float p = __expf(sc - m);
        l += p;
#pragma unroll
        for (int t = 0; t < 16; t++) {
            float4 vv = vrow[t];
            o[4 * t + 0] = fmaf(p, vv.x, o[4 * t + 0]);
            o[4 * t + 1] = fmaf(p, vv.y, o[4 * t + 1]);
            o[4 * t + 2] = fmaf(p, vv.z, o[4 * t + 2]);
            o[4 * t + 3] = fmaf(p, vv.w, o[4 * t + 3]);
        }
    } else {
        float c0 = __expf(m - sc);
        m = sc;
        l = fmaf(l, c0, 1.f);
#pragma unroll
        for (int t = 0; t < 16; t++) {
            float4 vv = vrow[t];
            o[4 * t + 0] = fmaf(o[4 * t + 0], c0, vv.x);
            o[4 * t + 1] = fmaf(o[4 * t + 1], c0, vv.y);
            o[4 * t + 2] = fmaf(o[4 * t + 2], c0, vv.z);
            o[4 * t + 3] = fmaf(o[4 * t + 3], c0, vv.w);
        }
    }
}

__global__ void __launch_bounds__(128) attn_kernel(
    const float* __restrict__ q, const float* __restrict__ k,
    const float* __restrict__ v, const float* __restrict__ gammas,
    float* __restrict__ out)
{
    __shared__ float4 ksh[TS * 16];
    __shared__ float4 vsh[TS * 16];

    int h = blockIdx.y;
    // Reverse mapping: heavy (high-qs, triangular) tiles launch first.
    int qtile = (int)(gridDim.x - 1u - blockIdx.x);
    int qs = qtile * 128;
    int tid = threadIdx.x;
    int i = qs + tid;

    float4 qr[16];
    {
        const float4* qg = reinterpret_cast<const float4*>(q + ((size_t)h * NN + i) * DD);
#pragma unroll
        for (int t = 0; t < 16; t++) qr[t] = qg[t];
    }

    float m = NEGINF, l = 0.f;
    float o[DD];
#pragma unroll
    for (int t = 0; t < DD; t++) o[t] = 0.f;

    // ---- Level 0: sliding window, keys [qs-128, qs+127], nearest-first ----
    {
        float g0 = gammas[0];
#pragma unroll 1
        for (int tb = qs + 128 - TS; tb >= qs - 128; tb -= TS) {
            __syncthreads();
            for (int e = tid; e < TS * 16; e += 128) {
                int row = e >> 4, col = e & 15;
                int j = tb + row;
                float4 kk = make_float4(0.f, 0.f, 0.f, 0.f), vv = kk;
                if (j >= 0) {
                    kk = reinterpret_cast<const float4*>(k + ((size_t)h * NN + j) * DD)[col];
                    vv = reinterpret_cast<const float4*>(v + ((size_t)h * NN + j) * DD)[col];
                }
                ksh[e] = kk; vsh[e] = vv;
            }
            __syncthreads();
#pragma unroll 1
            for (int r = TS - 1; r >= 0; r--) {
                int j = tb + r;
                int dist = i - j;
                if (j >= 0 && dist >= 0 && dist <= WW - 1) {
                    dot_update(&ksh[r * 16], &vsh[r * 16], qr,
                               -g0 * (float)dist, m, l, o);
                }
            }
        }
    }

    // ---- Levels 1..3: pooled chunks, nearest-first ----
#pragma unroll 1
    for (int lvl = 1; lvl <= 3; lvl++) {
        const float* kl; const float* vl; int C, S;
        if (lvl == 1)      { kl = g_k1 + (size_t)h * 1024 * DD; vl = g_v1 + (size_t)h * 1024 * DD; C = 1024; S = 8;   }
        else if (lvl == 2) { kl = g_k2 + (size_t)h * 128  * DD; vl = g_v2 + (size_t)h * 128  * DD; C = 128;  S = 64;  }
        else               { kl = g_k3 + (size_t)h * 16   * DD; vl = g_v3 + (size_t)h * 16   * DD; C = 16;   S = 512; }
        float g = gammas[lvl];
        // block-uniform bound: max visible chunk for i = qs+127 is qs/S - 1
        int cmax_blk = qs / S - 1;
        if (cmax_blk < 0) continue;
#pragma unroll 1
        for (int cb = (cmax_blk / TS) * TS; cb >= 0; cb -= TS) {
            __syncthreads();
            for (int e = tid; e < TS * 16; e += 128) {
                int row = e >> 4, col = e & 15;
                int c = cb + row;
                float4 kk = make_float4(0.f, 0.f, 0.f, 0.f), vv = kk;
                if (c < C) {
                    kk = reinterpret_cast<const float4*>(kl + (size_t)c * DD)[col];
                    vv = reinterpret_cast<const float4*>(vl + (size_t)c * DD)[col];
                }
                ksh[e] = kk; vsh[e] = vv;
            }
            __syncthreads();
#pragma unroll 1
            for (int r = TS - 1; r >= 0; r--) {
                int c = cb + r;
                int jlast = (c + 1) * S - 1;
                int dist = i - jlast;
                if (c < C && dist >= WW) {
                    dot_update(&ksh[r * 16], &vsh[r * 16], qr,
                               -g * (float)dist, m, l, o);
                }
            }
        }
    }

    // ---- write out = o / clip(l, 1e-8) ----
    float inv = 1.0f / fmaxf(l, 1e-8f);
    float4* og = reinterpret_cast<float4*>(out + ((size_t)h * NN + i) * DD);
#pragma unroll
    for (int t = 0; t < 16; t++) {
        og[t] = make_float4(o[4 * t + 0] * inv, o[4 * t + 1] * inv,
                            o[4 * t + 2] * inv, o[4 * t + 3] * inv);
    }
}

// ---------------- launch ----------------
extern "C" void kernel_launch(void* const* d_in, const int* in_sizes, int n_in,
                              void* d_out, int out_size) {
    const float* q      = (const float*)d_in[0];
    const float* k      = (const float*)d_in[1];
    const float* v      = (const float*)d_in[2];
    const float* gammas = (const float*)d_in[3];
    float* out = (float*)d_out;

    pool1_kernel<<<(HH * 1024 * DD + 255) / 256, 256>>>(k, v);
    pool2_kernel<<<(HH * 128 * DD + 255) / 256, 256>>>();
    pool3_kernel<<<(HH * 16 * DD + 255) / 256, 256>>>();

    dim3 grid(NN / 128, HH);
    attn_kernel<<<grid, 128>>>(q, k, v, gammas, out);
}